// round 6
// baseline (speedup 1.0000x reference)
#include <cuda_runtime.h>
#include <cuda_bf16.h>
#include <cstdint>
#include <cstddef>

// Problem constants
#define BB    32
#define DD    512
#define NN    4096
#define KK    64
#define DTILE 64           // d rows per CTA
#define NC    64           // n elements per stage (64 bf16 = 128B row)
#define NITER (NN / NC)    // 64

// SMEM stage layout: x tile 64 rows x 128B = 8KB, a tile 64 x 128B = 8KB
#define STG_BYTES  16384
#define STG_AOFF   8192
#define OFF_ASUM   (2 * STG_BYTES)          // 64 floats
#define SMEM_TOTAL (OFF_ASUM + 256 + 1024)  // + alignment slack

__device__ __forceinline__ uint32_t smem_u32(const void* p) {
    uint32_t a;
    asm("{ .reg .u64 t; cvta.to.shared.u64 t, %1; cvt.u32.u64 %0, t; }" : "=r"(a) : "l"(p));
    return a;
}

__device__ __forceinline__ void sts8(uint32_t addr, uint32_t a, uint32_t b) {
    asm volatile("st.shared.v2.b32 [%0], {%1, %2};" :: "r"(addr), "r"(a), "r"(b) : "memory");
}

__device__ __forceinline__ void sts16(uint32_t addr, float4 v) {
    asm volatile("st.shared.v4.b32 [%0], {%1, %2, %3, %4};"
                 :: "r"(addr), "f"(v.x), "f"(v.y), "f"(v.z), "f"(v.w) : "memory");
}

__device__ __forceinline__ float4 lds16(uint32_t addr) {
    float4 v;
    asm volatile("ld.shared.v4.b32 {%0, %1, %2, %3}, [%4];"
                 : "=f"(v.x), "=f"(v.y), "=f"(v.z), "=f"(v.w) : "r"(addr));
    return v;
}

__device__ __forceinline__ void ldsm4(uint32_t* r, uint32_t addr) {
    asm volatile("ldmatrix.sync.aligned.m8n8.x4.shared.b16 {%0,%1,%2,%3}, [%4];"
                 : "=r"(r[0]), "=r"(r[1]), "=r"(r[2]), "=r"(r[3]) : "r"(addr));
}

__device__ __forceinline__ void mma16816(float* d, const uint32_t* a, uint32_t b0, uint32_t b1) {
    asm volatile(
        "mma.sync.aligned.m16n8k16.row.col.f32.bf16.bf16.f32 "
        "{%0,%1,%2,%3}, {%4,%5,%6,%7}, {%8,%9}, {%0,%1,%2,%3};"
        : "+f"(d[0]), "+f"(d[1]), "+f"(d[2]), "+f"(d[3])
        : "r"(a[0]), "r"(a[1]), "r"(a[2]), "r"(a[3]), "r"(b0), "r"(b1));
}

__device__ __forceinline__ void cvt4(const float4& v, uint32_t& lo, uint32_t& hi) {
    __nv_bfloat162 l = __floats2bfloat162_rn(v.x, v.y);
    __nv_bfloat162 h = __floats2bfloat162_rn(v.z, v.w);
    lo = *reinterpret_cast<uint32_t*>(&l);
    hi = *reinterpret_cast<uint32_t*>(&h);
}

// ---------------------------------------------------------------------------
// Single fused kernel. Per CTA (b, dt): D[64 d, 64 k] = X(64 x n) @ Abar^T
// via mma.sync bf16. 256 threads / 8 warps; warp grid 2(m) x 2(n) x 2(nsplit):
// each warp owns a 32x32 tile over half of each stage's contraction steps
// (cuts ldmatrix re-reads: A x2, B x2 instead of x2/x4). Prefetch distance 2:
// regs drained (STS) at iteration top, refilled (LDG) right after -> LDG has
// a full iteration to complete. a_sum folded into the LDG stream. Epilogue
// (after cross-warp nsplit reduction): V = wx - a_sum[k]*c[k,d] -> out[d,k,b].
// ---------------------------------------------------------------------------
__global__ void __launch_bounds__(256, 2)
vlad_main(const float* __restrict__ x, const float* __restrict__ ab,
          const float* __restrict__ cmat, float* __restrict__ out) {
    extern __shared__ __align__(16) char smem_raw[];
    const uint32_t sbr = smem_u32(smem_raw);
    const uint32_t sb0 = (sbr + 1023) & ~1023u;
    float* asum_s = reinterpret_cast<float*>(smem_raw + (sb0 - sbr) + OFF_ASUM);

    const int tid  = threadIdx.x;
    const int warp = tid >> 5, lane = tid & 31;
    const int b  = blockIdx.x >> 3;
    const int dt = blockIdx.x & 7;

    const float* xbase = x  + ((size_t)b * DD + (size_t)dt * DTILE) * NN;
    const float* abase = ab + (size_t)b * KK * NN;

    // STS swizzled offsets: 1024 float4 per tile, 4/thread; ci = tid + 256j.
    uint32_t sts_off[4];
#pragma unroll
    for (int j = 0; j < 4; j++) {
        int ci = tid + 256 * j, row = ci >> 4, c4 = ci & 15;
        uint32_t off = (uint32_t)((row << 7) + (c4 << 3));
        sts_off[j] = off ^ ((off >> 3) & 0x70);
    }

    // Warp decomposition: 2(m) x 2(n) x 2(nsplit)
    const int wm = (warp & 1) * 32;
    const int wn = ((warp >> 1) & 1) * 32;
    const int nh = warp >> 2;                 // contraction half: k-steps 2nh, 2nh+1

    // ldmatrix source offsets
    const int g = lane >> 3, r = lane & 7;
    uint32_t offA[2], offB[2];
#pragma unroll
    for (int i = 0; i < 2; i++) {
        int row = wm + i * 16 + (g & 1) * 8 + r;
        uint32_t gk = (uint32_t)((g >> 1) * 16);
        offA[i] = (uint32_t)(row << 7) + (gk ^ (uint32_t)((row & 7) << 4));
    }
#pragma unroll
    for (int nb = 0; nb < 2; nb++) {
        int row = wn + nb * 16 + (g >> 1) * 8 + r;
        uint32_t gk = (uint32_t)((g & 1) * 16);
        offB[nb] = (uint32_t)(row << 7) + (gk ^ (uint32_t)((row & 7) << 4)) + STG_AOFF;
    }

    // Accumulators: 2 m-frags x 4 n-frags, one float4 each = 32 regs
    float4 accv[8];
#pragma unroll
    for (int i = 0; i < 8; i++) accv[i] = make_float4(0.f, 0.f, 0.f, 0.f);
    float asum_p[4] = {0.f, 0.f, 0.f, 0.f};

    float4 xr[4], ar[4];

    // ---- prologue ----
    // load stage 0, store to buf0, load stage 1 (regs carry stage 1 into loop)
#pragma unroll
    for (int j = 0; j < 4; j++) {
        int ci = tid + 256 * j, row = ci >> 4, c4 = ci & 15;
        xr[j] = *reinterpret_cast<const float4*>(xbase + (size_t)row * NN + (c4 << 2));
        ar[j] = *reinterpret_cast<const float4*>(abase + (size_t)row * NN + (c4 << 2));
    }
#pragma unroll
    for (int j = 0; j < 4; j++) {
        uint32_t lo, hi;
        cvt4(xr[j], lo, hi); sts8(sb0 + sts_off[j], lo, hi);
        cvt4(ar[j], lo, hi); sts8(sb0 + STG_AOFF + sts_off[j], lo, hi);
        asum_p[j] += (ar[j].x + ar[j].y) + (ar[j].z + ar[j].w);
    }
#pragma unroll
    for (int j = 0; j < 4; j++) {
        int ci = tid + 256 * j, row = ci >> 4, c4 = ci & 15;
        xr[j] = *reinterpret_cast<const float4*>(xbase + (size_t)row * NN + NC + (c4 << 2));
        ar[j] = *reinterpret_cast<const float4*>(abase + (size_t)row * NN + NC + (c4 << 2));
    }
#pragma unroll
    for (int j = 0; j < 4; j++)
        asum_p[j] += (ar[j].x + ar[j].y) + (ar[j].z + ar[j].w);

    for (int it = 0; it < NITER; ++it) {
        __syncthreads();

        // Drain regs: store stage it+1 into buf (it+1)&1
        if (it + 1 < NITER) {
            const uint32_t ns = sb0 + (uint32_t)((it + 1) & 1) * STG_BYTES;
#pragma unroll
            for (int j = 0; j < 4; j++) {
                uint32_t lo, hi;
                cvt4(xr[j], lo, hi); sts8(ns + sts_off[j], lo, hi);
                cvt4(ar[j], lo, hi); sts8(ns + STG_AOFF + sts_off[j], lo, hi);
            }
        }

        // Refill regs: load stage it+2 (a full iteration to complete)
        if (it + 2 < NITER) {
            const int nb2 = (it + 2) * NC;
#pragma unroll
            for (int j = 0; j < 4; j++) {
                int ci = tid + 256 * j, row = ci >> 4, c4 = ci & 15;
                xr[j] = *reinterpret_cast<const float4*>(xbase + (size_t)row * NN + nb2 + (c4 << 2));
                ar[j] = *reinterpret_cast<const float4*>(abase + (size_t)row * NN + nb2 + (c4 << 2));
            }
        }

        // Compute stage it from buf it&1 (this warp's contraction half only)
        const uint32_t bs = sb0 + (uint32_t)(it & 1) * STG_BYTES;
#pragma unroll
        for (int s2 = 0; s2 < 2; s2++) {
            const uint32_t kx = (uint32_t)((2 * nh + s2) << 5);
            uint32_t aF0[4], aF1[4], bF0[4], bF1[4];
            ldsm4(aF0, (bs + offA[0]) ^ kx);
            ldsm4(aF1, (bs + offA[1]) ^ kx);
            ldsm4(bF0, (bs + offB[0]) ^ kx);
            ldsm4(bF1, (bs + offB[1]) ^ kx);
            mma16816(reinterpret_cast<float*>(&accv[0]), aF0, bF0[0], bF0[1]);
            mma16816(reinterpret_cast<float*>(&accv[1]), aF0, bF0[2], bF0[3]);
            mma16816(reinterpret_cast<float*>(&accv[2]), aF0, bF1[0], bF1[1]);
            mma16816(reinterpret_cast<float*>(&accv[3]), aF0, bF1[2], bF1[3]);
            mma16816(reinterpret_cast<float*>(&accv[4]), aF1, bF0[0], bF0[1]);
            mma16816(reinterpret_cast<float*>(&accv[5]), aF1, bF0[2], bF0[3]);
            mma16816(reinterpret_cast<float*>(&accv[6]), aF1, bF1[0], bF1[1]);
            mma16816(reinterpret_cast<float*>(&accv[7]), aF1, bF1[2], bF1[3]);
        }

        // Fold a into running a_sum (stage it+2, loaded above)
        if (it + 2 < NITER) {
#pragma unroll
            for (int j = 0; j < 4; j++)
                asum_p[j] += (ar[j].x + ar[j].y) + (ar[j].z + ar[j].w);
        }
    }

    // ---- a_sum reduction: k = (tid + 256j) >> 4; 16 consecutive lanes share ----
#pragma unroll
    for (int j = 0; j < 4; j++) {
#pragma unroll
        for (int o = 1; o < 16; o <<= 1)
            asum_p[j] += __shfl_xor_sync(0xFFFFFFFFu, asum_p[j], o);
    }
    if ((lane & 15) == 0) {
        int q = tid >> 4;
#pragma unroll
        for (int j = 0; j < 4; j++) asum_s[q + 16 * j] = asum_p[j];
    }

    // ---- nsplit reduction: warps 4-7 hand partial accs to warps 0-3 ----
    if (nh == 1) {
#pragma unroll
        for (int j4 = 0; j4 < 8; j4++)
            sts16(sb0 + (uint32_t)(j4 * 2048 + (tid & 127) * 16), accv[j4]);
    }
    __syncthreads();

    if (nh == 0) {
#pragma unroll
        for (int j4 = 0; j4 < 8; j4++) {
            float4 p = lds16(sb0 + (uint32_t)(j4 * 2048 + (tid & 127) * 16));
            accv[j4].x += p.x; accv[j4].y += p.y; accv[j4].z += p.z; accv[j4].w += p.w;
        }

        // ---- epilogue: V = wx - a_sum[k]*c[k,d], out[d,k,b] ----
        const int mrow = lane >> 2, ncol = (lane & 3) * 2;
#pragma unroll
        for (int i = 0; i < 2; i++) {
#pragma unroll
            for (int j = 0; j < 4; j++) {
                const float* ap = reinterpret_cast<const float*>(&accv[i * 4 + j]);
                const int k0 = wn + j * 8 + ncol;
                const int d0 = dt * DTILE + wm + i * 16 + mrow;
                const float as0 = asum_s[k0], as1 = asum_s[k0 + 1];
#pragma unroll
                for (int rr = 0; rr < 2; rr++) {
                    const int d = d0 + rr * 8;
                    float v0 = ap[rr * 2 + 0] - as0 * __ldg(cmat + (size_t)k0 * DD + d);
                    float v1 = ap[rr * 2 + 1] - as1 * __ldg(cmat + (size_t)(k0 + 1) * DD + d);
                    out[(size_t)d * KK * BB + (size_t)k0 * BB + b] = v0;
                    out[(size_t)d * KK * BB + (size_t)(k0 + 1) * BB + b] = v1;
                }
            }
        }
    }
}

extern "C" void kernel_launch(void* const* d_in, const int* in_sizes, int n_in,
                              void* d_out, int out_size) {
    (void)in_sizes; (void)n_in; (void)out_size;
    const float* x  = (const float*)d_in[0];
    const float* ab = (const float*)d_in[1];
    const float* c  = (const float*)d_in[2];
    float* out = (float*)d_out;

    cudaFuncSetAttribute(vlad_main, cudaFuncAttributeMaxDynamicSharedMemorySize, SMEM_TOTAL);
    vlad_main<<<BB * 8, 256, SMEM_TOTAL>>>(x, ab, c, out);
}

// round 7
// speedup vs baseline: 1.0549x; 1.0549x over previous
#include <cuda_runtime.h>
#include <cuda_bf16.h>
#include <cstdint>
#include <cstddef>

// Problem constants
#define BB    32
#define DD    512
#define NN    4096
#define KK    64
#define DTILE 64           // d rows per CTA
#define NC    64           // n elements per stage (64 bf16 = 128B row)
#define NITER (NN / NC)    // 64

// SMEM stage layout: x tile 64 rows x 128B = 8KB, a tile 64 x 128B = 8KB
#define STG_BYTES  16384
#define STG_AOFF   8192
#define OFF_ASUM   (2 * STG_BYTES)          // 64 floats
#define SMEM_TOTAL (OFF_ASUM + 256 + 1024)  // + alignment slack

__device__ __forceinline__ uint32_t smem_u32(const void* p) {
    uint32_t a;
    asm("{ .reg .u64 t; cvta.to.shared.u64 t, %1; cvt.u32.u64 %0, t; }" : "=r"(a) : "l"(p));
    return a;
}

__device__ __forceinline__ void sts16u(uint32_t addr, uint32_t a, uint32_t b,
                                       uint32_t c, uint32_t d) {
    asm volatile("st.shared.v4.b32 [%0], {%1, %2, %3, %4};"
                 :: "r"(addr), "r"(a), "r"(b), "r"(c), "r"(d) : "memory");
}

__device__ __forceinline__ void sts16(uint32_t addr, float4 v) {
    asm volatile("st.shared.v4.b32 [%0], {%1, %2, %3, %4};"
                 :: "r"(addr), "f"(v.x), "f"(v.y), "f"(v.z), "f"(v.w) : "memory");
}

__device__ __forceinline__ float4 lds16(uint32_t addr) {
    float4 v;
    asm volatile("ld.shared.v4.b32 {%0, %1, %2, %3}, [%4];"
                 : "=f"(v.x), "=f"(v.y), "=f"(v.z), "=f"(v.w) : "r"(addr));
    return v;
}

__device__ __forceinline__ void ldsm4(uint32_t* r, uint32_t addr) {
    asm volatile("ldmatrix.sync.aligned.m8n8.x4.shared.b16 {%0,%1,%2,%3}, [%4];"
                 : "=r"(r[0]), "=r"(r[1]), "=r"(r[2]), "=r"(r[3]) : "r"(addr));
}

__device__ __forceinline__ void mma16816(float* d, const uint32_t* a, uint32_t b0, uint32_t b1) {
    asm volatile(
        "mma.sync.aligned.m16n8k16.row.col.f32.bf16.bf16.f32 "
        "{%0,%1,%2,%3}, {%4,%5,%6,%7}, {%8,%9}, {%0,%1,%2,%3};"
        : "+f"(d[0]), "+f"(d[1]), "+f"(d[2]), "+f"(d[3])
        : "r"(a[0]), "r"(a[1]), "r"(a[2]), "r"(a[3]), "r"(b0), "r"(b1));
}

__device__ __forceinline__ uint32_t cvt2(float a, float b) {
    __nv_bfloat162 p = __floats2bfloat162_rn(a, b);
    return *reinterpret_cast<uint32_t*>(&p);
}

// ---------------------------------------------------------------------------
// Single fused kernel. Per CTA (b, dt): D[64 d, 64 k] = X(64 x n) @ Abar^T
// via mma.sync bf16. Warp grid 2(m) x 2(n) x 2(nsplit). Key scheduling rule:
// NOTHING inside iteration `it` consumes LDGs issued in iteration `it`.
//   sync -> cvt+STS stage it+1 (regs 1 iter old) + asum fold (same regs,
//   pinned before the LDG refill by WAR) -> LDG stage it+2 -> compute it.
// Per-thread global reads are 32B-contiguous chunks (2x LDG.128 -> STS.128).
// Epilogue: V = wx - a_sum[k]*c[k,d] -> out[d,k,b].
// ---------------------------------------------------------------------------
__global__ void __launch_bounds__(256, 2)
vlad_main(const float* __restrict__ x, const float* __restrict__ ab,
          const float* __restrict__ cmat, float* __restrict__ out) {
    extern __shared__ __align__(16) char smem_raw[];
    const uint32_t sbr = smem_u32(smem_raw);
    const uint32_t sb0 = (sbr + 1023) & ~1023u;
    float* asum_s = reinterpret_cast<float*>(smem_raw + (sb0 - sbr) + OFF_ASUM);

    const int tid  = threadIdx.x;
    const int warp = tid >> 5, lane = tid & 31;
    const int b  = blockIdx.x >> 3;
    const int dt = blockIdx.x & 7;

    // 32B-chunk mapping: piece j in {0,1}: idx = tid + 256j ->
    //   row = idx>>3 = (tid>>3) + 32j, c8 = idx&7 (constant across j)
    const int row0 = tid >> 3, c8 = tid & 7;
    const float* xp0 = x  + ((size_t)b * DD + (size_t)dt * DTILE + row0) * NN + c8 * 8;
    const float* xp1 = xp0 + (size_t)32 * NN;
    const float* ap0 = ab + ((size_t)b * KK + row0) * NN + c8 * 8;
    const float* ap1 = ap0 + (size_t)32 * NN;

    // STS swizzled offset for piece 0; piece 1 = +4096 (row+32 keeps row&7)
    uint32_t sw0;
    {
        uint32_t off = (uint32_t)((row0 << 7) + (c8 << 4));
        sw0 = off ^ ((uint32_t)(row0 & 7) << 4);
    }

    // Warp decomposition: 2(m) x 2(n) x 2(nsplit)
    const int wm = (warp & 1) * 32;
    const int wn = ((warp >> 1) & 1) * 32;
    const int nh = warp >> 2;

    // ldmatrix source offsets
    const int g = lane >> 3, r = lane & 7;
    uint32_t offA[2], offB[2];
#pragma unroll
    for (int i = 0; i < 2; i++) {
        int row = wm + i * 16 + (g & 1) * 8 + r;
        uint32_t gk = (uint32_t)((g >> 1) * 16);
        offA[i] = (uint32_t)(row << 7) + (gk ^ (uint32_t)((row & 7) << 4));
    }
#pragma unroll
    for (int nb = 0; nb < 2; nb++) {
        int row = wn + nb * 16 + (g >> 1) * 8 + r;
        uint32_t gk = (uint32_t)((g & 1) * 16);
        offB[nb] = (uint32_t)(row << 7) + (gk ^ (uint32_t)((row & 7) << 4)) + STG_AOFF;
    }

    float4 accv[8];
#pragma unroll
    for (int i = 0; i < 8; i++) accv[i] = make_float4(0.f, 0.f, 0.f, 0.f);
    float asum_p[2] = {0.f, 0.f};

    float4 xr[4], ar[4];     // xr[2j],xr[2j+1] = piece j (32B); same for ar

    // ---- prologue ----
    // stage 0: load, fold, cvt+STS into buf0
    xr[0] = *reinterpret_cast<const float4*>(xp0);
    xr[1] = *reinterpret_cast<const float4*>(xp0 + 4);
    xr[2] = *reinterpret_cast<const float4*>(xp1);
    xr[3] = *reinterpret_cast<const float4*>(xp1 + 4);
    ar[0] = *reinterpret_cast<const float4*>(ap0);
    ar[1] = *reinterpret_cast<const float4*>(ap0 + 4);
    ar[2] = *reinterpret_cast<const float4*>(ap1);
    ar[3] = *reinterpret_cast<const float4*>(ap1 + 4);
#pragma unroll
    for (int j = 0; j < 2; j++) {
        asum_p[j] += (ar[2*j].x + ar[2*j].y) + (ar[2*j].z + ar[2*j].w)
                   + (ar[2*j+1].x + ar[2*j+1].y) + (ar[2*j+1].z + ar[2*j+1].w);
        sts16u(sb0 + sw0 + (uint32_t)(j * 4096),
               cvt2(xr[2*j].x, xr[2*j].y),   cvt2(xr[2*j].z, xr[2*j].w),
               cvt2(xr[2*j+1].x, xr[2*j+1].y), cvt2(xr[2*j+1].z, xr[2*j+1].w));
        sts16u(sb0 + STG_AOFF + sw0 + (uint32_t)(j * 4096),
               cvt2(ar[2*j].x, ar[2*j].y),   cvt2(ar[2*j].z, ar[2*j].w),
               cvt2(ar[2*j+1].x, ar[2*j+1].y), cvt2(ar[2*j+1].z, ar[2*j+1].w));
    }
    // stage 1: load into regs (STS'd + folded at it=0)
    xr[0] = *reinterpret_cast<const float4*>(xp0 + NC);
    xr[1] = *reinterpret_cast<const float4*>(xp0 + NC + 4);
    xr[2] = *reinterpret_cast<const float4*>(xp1 + NC);
    xr[3] = *reinterpret_cast<const float4*>(xp1 + NC + 4);
    ar[0] = *reinterpret_cast<const float4*>(ap0 + NC);
    ar[1] = *reinterpret_cast<const float4*>(ap0 + NC + 4);
    ar[2] = *reinterpret_cast<const float4*>(ap1 + NC);
    ar[3] = *reinterpret_cast<const float4*>(ap1 + NC + 4);

    for (int it = 0; it < NITER; ++it) {
        __syncthreads();

        // (1) Drain: cvt + STS stage it+1 (regs 1 iteration old) + asum fold.
        //     The fold reads ar BEFORE the LDG below overwrites it (WAR),
        //     so it can never stall on in-flight loads.
        if (it + 1 < NITER) {
            const uint32_t ns = sb0 + (uint32_t)((it + 1) & 1) * STG_BYTES;
#pragma unroll
            for (int j = 0; j < 2; j++) {
                asum_p[j] += (ar[2*j].x + ar[2*j].y) + (ar[2*j].z + ar[2*j].w)
                           + (ar[2*j+1].x + ar[2*j+1].y) + (ar[2*j+1].z + ar[2*j+1].w);
                sts16u(ns + sw0 + (uint32_t)(j * 4096),
                       cvt2(xr[2*j].x, xr[2*j].y),   cvt2(xr[2*j].z, xr[2*j].w),
                       cvt2(xr[2*j+1].x, xr[2*j+1].y), cvt2(xr[2*j+1].z, xr[2*j+1].w));
                sts16u(ns + STG_AOFF + sw0 + (uint32_t)(j * 4096),
                       cvt2(ar[2*j].x, ar[2*j].y),   cvt2(ar[2*j].z, ar[2*j].w),
                       cvt2(ar[2*j+1].x, ar[2*j+1].y), cvt2(ar[2*j+1].z, ar[2*j+1].w));
            }
        }

        // (2) Refill: LDG stage it+2 (no consumer this iteration)
        if (it + 2 < NITER) {
            const int nb2 = (it + 2) * NC;
            xr[0] = *reinterpret_cast<const float4*>(xp0 + nb2);
            xr[1] = *reinterpret_cast<const float4*>(xp0 + nb2 + 4);
            xr[2] = *reinterpret_cast<const float4*>(xp1 + nb2);
            xr[3] = *reinterpret_cast<const float4*>(xp1 + nb2 + 4);
            ar[0] = *reinterpret_cast<const float4*>(ap0 + nb2);
            ar[1] = *reinterpret_cast<const float4*>(ap0 + nb2 + 4);
            ar[2] = *reinterpret_cast<const float4*>(ap1 + nb2);
            ar[3] = *reinterpret_cast<const float4*>(ap1 + nb2 + 4);
        }

        // (3) Compute stage it from buf it&1 (this warp's contraction half)
        const uint32_t bs = sb0 + (uint32_t)(it & 1) * STG_BYTES;
#pragma unroll
        for (int s2 = 0; s2 < 2; s2++) {
            const uint32_t kx = (uint32_t)((2 * nh + s2) << 5);
            uint32_t aF0[4], aF1[4], bF0[4], bF1[4];
            ldsm4(aF0, (bs + offA[0]) ^ kx);
            ldsm4(aF1, (bs + offA[1]) ^ kx);
            ldsm4(bF0, (bs + offB[0]) ^ kx);
            ldsm4(bF1, (bs + offB[1]) ^ kx);
            mma16816(reinterpret_cast<float*>(&accv[0]), aF0, bF0[0], bF0[1]);
            mma16816(reinterpret_cast<float*>(&accv[1]), aF0, bF0[2], bF0[3]);
            mma16816(reinterpret_cast<float*>(&accv[2]), aF0, bF1[0], bF1[1]);
            mma16816(reinterpret_cast<float*>(&accv[3]), aF0, bF1[2], bF1[3]);
            mma16816(reinterpret_cast<float*>(&accv[4]), aF1, bF0[0], bF0[1]);
            mma16816(reinterpret_cast<float*>(&accv[5]), aF1, bF0[2], bF0[3]);
            mma16816(reinterpret_cast<float*>(&accv[6]), aF1, bF1[0], bF1[1]);
            mma16816(reinterpret_cast<float*>(&accv[7]), aF1, bF1[2], bF1[3]);
        }
    }

    // ---- a_sum reduction: piece j covers k = row0 + 32j; 8 threads (same
    // row0, c8 0..7) share a k -> xor-reduce offsets 1,2,4 within 8 lanes ----
#pragma unroll
    for (int j = 0; j < 2; j++) {
#pragma unroll
        for (int o = 1; o < 8; o <<= 1)
            asum_p[j] += __shfl_xor_sync(0xFFFFFFFFu, asum_p[j], o);
    }
    if ((lane & 7) == 0) {
        asum_s[row0]      = asum_p[0];
        asum_s[row0 + 32] = asum_p[1];
    }

    // ---- nsplit reduction: warps 4-7 hand partial accs to warps 0-3 ----
    if (nh == 1) {
#pragma unroll
        for (int j4 = 0; j4 < 8; j4++)
            sts16(sb0 + (uint32_t)(j4 * 2048 + (tid & 127) * 16), accv[j4]);
    }
    __syncthreads();

    if (nh == 0) {
#pragma unroll
        for (int j4 = 0; j4 < 8; j4++) {
            float4 p = lds16(sb0 + (uint32_t)(j4 * 2048 + (tid & 127) * 16));
            accv[j4].x += p.x; accv[j4].y += p.y; accv[j4].z += p.z; accv[j4].w += p.w;
        }

        // ---- epilogue: V = wx - a_sum[k]*c[k,d], out[d,k,b] ----
        const int mrow = lane >> 2, ncol = (lane & 3) * 2;
#pragma unroll
        for (int i = 0; i < 2; i++) {
#pragma unroll
            for (int j = 0; j < 4; j++) {
                const float* ap = reinterpret_cast<const float*>(&accv[i * 4 + j]);
                const int k0 = wn + j * 8 + ncol;
                const int d0 = dt * DTILE + wm + i * 16 + mrow;
                const float as0 = asum_s[k0], as1 = asum_s[k0 + 1];
#pragma unroll
                for (int rr = 0; rr < 2; rr++) {
                    const int d = d0 + rr * 8;
                    float v0 = ap[rr * 2 + 0] - as0 * __ldg(cmat + (size_t)k0 * DD + d);
                    float v1 = ap[rr * 2 + 1] - as1 * __ldg(cmat + (size_t)(k0 + 1) * DD + d);
                    out[(size_t)d * KK * BB + (size_t)k0 * BB + b] = v0;
                    out[(size_t)d * KK * BB + (size_t)(k0 + 1) * BB + b] = v1;
                }
            }
        }
    }
}

extern "C" void kernel_launch(void* const* d_in, const int* in_sizes, int n_in,
                              void* d_out, int out_size) {
    (void)in_sizes; (void)n_in; (void)out_size;
    const float* x  = (const float*)d_in[0];
    const float* ab = (const float*)d_in[1];
    const float* c  = (const float*)d_in[2];
    float* out = (float*)d_out;

    cudaFuncSetAttribute(vlad_main, cudaFuncAttributeMaxDynamicSharedMemorySize, SMEM_TOTAL);
    vlad_main<<<BB * 8, 256, SMEM_TOTAL>>>(x, ab, c, out);
}